// round 15
// baseline (speedup 1.0000x reference)
#include <cuda_runtime.h>
#include <math.h>

#define BATCH 128
#define SEQ 48
#define FEAT 60
#define NH 5
#define NV 6
#define TWO_PI 6.2831853071795864769f

// ---- batch-invariant precomputed data (written by prep kernel) ----
__device__ float g_Rr[32*32];   // row-major, embed-phase folded
__device__ float g_Ri[32*32];
__device__ float g_CDE[18];     // Cc[6], Dd[6], Ee[6]

struct C2 { float re, im; };
struct M2 { C2 m00, m01, m10, m11; };

__device__ __forceinline__ C2 cmul(C2 a, C2 b) {
    C2 r; r.re = a.re*b.re - a.im*b.im; r.im = a.re*b.im + a.im*b.re; return r;
}
__device__ __forceinline__ C2 cadd(C2 a, C2 b) { C2 r{a.re+b.re, a.im+b.im}; return r; }

// U = RZ(t3) * RY(t2) * RX(t1)
__device__ __forceinline__ M2 fuse_zyx(float t1, float t2, float t3) {
    float c1,s1,c2,s2,c3,s3;
    sincosf(0.5f*t1, &s1, &c1);
    sincosf(0.5f*t2, &s2, &c2);
    sincosf(0.5f*t3, &s3, &c3);
    C2 a00{c1,0.f}, a01{0.f,-s1}, a10{0.f,-s1}, a11{c1,0.f};
    C2 m00{c2*a00.re - s2*a10.re, c2*a00.im - s2*a10.im};
    C2 m01{c2*a01.re - s2*a11.re, c2*a01.im - s2*a11.im};
    C2 m10{s2*a00.re + c2*a10.re, s2*a00.im + c2*a10.im};
    C2 m11{s2*a01.re + c2*a11.re, s2*a01.im + c2*a11.im};
    C2 r0{c3,-s3}, r1{c3,s3};
    M2 u;
    u.m00 = cmul(r0,m00); u.m01 = cmul(r0,m01);
    u.m10 = cmul(r1,m10); u.m11 = cmul(r1,m11);
    return u;
}
__device__ __forceinline__ M2 mmul(M2 p, M2 q) {
    M2 r;
    r.m00 = cadd(cmul(p.m00,q.m00), cmul(p.m01,q.m10));
    r.m01 = cadd(cmul(p.m00,q.m01), cmul(p.m01,q.m11));
    r.m10 = cadd(cmul(p.m10,q.m00), cmul(p.m11,q.m10));
    r.m11 = cadd(cmul(p.m10,q.m01), cmul(p.m11,q.m11));
    return r;
}

__device__ __forceinline__ M2 load_gate(const float* gm) {
    M2 g;
    g.m00.re = gm[0]; g.m00.im = gm[1];
    g.m01.re = gm[2]; g.m01.im = gm[3];
    g.m10.re = gm[4]; g.m10.im = gm[5];
    g.m11.re = gm[6]; g.m11.im = gm[7];
    return g;
}

// ---- cooperative SMEM gate stages: state S[amp][col], stride 33 ----
template<int M>
__device__ __forceinline__ void g1q_s(float* Sre, float* Sim, int col, int w, const float* gm) {
    M2 g = load_gate(gm);
    #pragma unroll
    for (int pp = 0; pp < 4; ++pp) {
        int p = 4*w + pp;
        int i = ((p & ~(M-1)) << 1) | (p & (M-1));
        int j = i | M;
        float ar = Sre[i*33+col], ai = Sim[i*33+col];
        float br = Sre[j*33+col], bi = Sim[j*33+col];
        Sre[i*33+col] = g.m00.re*ar - g.m00.im*ai + g.m01.re*br - g.m01.im*bi;
        Sim[i*33+col] = g.m00.re*ai + g.m00.im*ar + g.m01.re*bi + g.m01.im*br;
        Sre[j*33+col] = g.m10.re*ar - g.m10.im*ai + g.m11.re*br - g.m11.im*bi;
        Sim[j*33+col] = g.m10.re*ai + g.m10.im*ar + g.m11.re*bi + g.m11.im*br;
    }
}
template<int MC, int MT>
__device__ __forceinline__ void gcrx_s(float* Sre, float* Sim, int col, int w, float c, float s) {
    #pragma unroll
    for (int pp = 0; pp < 2; ++pp) {
        int p = 2*w + pp;
        int i = ((p & ~(MT-1)) << 2) | MC | (p & (MT-1));
        int j = i | MT;
        float a0r = Sre[i*33+col], a0i = Sim[i*33+col];
        float a1r = Sre[j*33+col], a1i = Sim[j*33+col];
        Sre[i*33+col] = c*a0r + s*a1i;
        Sim[i*33+col] = c*a0i - s*a1r;
        Sre[j*33+col] = s*a0i + c*a1r;
        Sim[j*33+col] = c*a1i - s*a0r;
    }
}

// ================= prep kernel: 1 CTA builds all batch-invariant data =================
__global__ __launch_bounds__(128)
void qrnn_prep(const float* __restrict__ params)
{
    const int tid = threadIdx.x;
    const int col = tid & 31;
    const int w   = tid >> 5;

    __shared__ float Sre[32*33];
    __shared__ float Sim[32*33];
    __shared__ float GM[10][8];
    __shared__ float CXs[8], SXs[8];

    // Phase A: cooperative parameter trig
    if (tid < 10) {
        int l = tid / 5, q = tid % 5;
        M2 g = fuse_zyx(params[l*37 + 3*q], params[l*37 + 3*q + 1], params[l*37 + 3*q + 2]);
        float* gm = GM[tid];
        gm[0] = g.m00.re; gm[1] = g.m00.im;
        gm[2] = g.m01.re; gm[3] = g.m01.im;
        gm[4] = g.m10.re; gm[5] = g.m10.im;
        gm[6] = g.m11.re; gm[7] = g.m11.im;
    } else if (tid < 18) {
        int k = tid - 10;
        int l = k >> 2, kk = k & 3;
        sincosf(0.5f*params[l*37 + 15 + kk], &SXs[k], &CXs[k]);
    } else if (tid >= 32 && tid < 38) {
        int q = tid - 32;
        M2 u0 = fuse_zyx(params[19+3*q],    params[20+3*q],    params[21+3*q]);
        M2 u1 = fuse_zyx(params[37+19+3*q], params[37+20+3*q], params[37+21+3*q]);
        M2 M = mmul(u1, u0);
        float h00 = (M.m00.re*M.m00.re + M.m00.im*M.m00.im)
                  - (M.m10.re*M.m10.re + M.m10.im*M.m10.im);
        float h11 = (M.m01.re*M.m01.re + M.m01.im*M.m01.im)
                  - (M.m11.re*M.m11.re + M.m11.im*M.m11.im);
        float imh01 = (M.m00.re*M.m01.im - M.m00.im*M.m01.re)
                    - (M.m10.re*M.m11.im - M.m10.im*M.m11.re);
        g_CDE[q]      = 0.5f*(h00 + h11);
        g_CDE[6 + q]  = 0.5f*(h00 - h11);
        g_CDE[12 + q] = imh01;
    }

    #pragma unroll
    for (int r = 0; r < 8; ++r) {
        int i = 8*w + r;
        Sre[i*33 + col] = (i == col) ? 1.f : 0.f;
        Sim[i*33 + col] = 0.f;
    }
    __syncthreads();

    // Phase B: U'' = CRX1*G2*CRX0*G1
    g1q_s<16>(Sre, Sim, col, w, GM[0]); __syncthreads();
    g1q_s< 8>(Sre, Sim, col, w, GM[1]); __syncthreads();
    g1q_s< 4>(Sre, Sim, col, w, GM[2]); __syncthreads();
    g1q_s< 2>(Sre, Sim, col, w, GM[3]); __syncthreads();
    g1q_s< 1>(Sre, Sim, col, w, GM[4]); __syncthreads();
    gcrx_s<16,8>(Sre, Sim, col, w, CXs[0], SXs[0]); __syncthreads();
    gcrx_s< 8,4>(Sre, Sim, col, w, CXs[1], SXs[1]); __syncthreads();
    gcrx_s< 4,2>(Sre, Sim, col, w, CXs[2], SXs[2]); __syncthreads();
    gcrx_s< 2,1>(Sre, Sim, col, w, CXs[3], SXs[3]); __syncthreads();
    g1q_s<16>(Sre, Sim, col, w, GM[5]); __syncthreads();
    g1q_s< 8>(Sre, Sim, col, w, GM[6]); __syncthreads();
    g1q_s< 4>(Sre, Sim, col, w, GM[7]); __syncthreads();
    g1q_s< 2>(Sre, Sim, col, w, GM[8]); __syncthreads();
    g1q_s< 1>(Sre, Sim, col, w, GM[9]); __syncthreads();
    gcrx_s<16,8>(Sre, Sim, col, w, CXs[4], SXs[4]); __syncthreads();
    gcrx_s< 8,4>(Sre, Sim, col, w, CXs[5], SXs[5]); __syncthreads();
    gcrx_s< 4,2>(Sre, Sim, col, w, CXs[6], SXs[6]); __syncthreads();
    gcrx_s< 2,1>(Sre, Sim, col, w, CXs[7], SXs[7]); __syncthreads();

    // store rows to global with embed phase (-i)^popc(col) folded
    #pragma unroll
    for (int e = 0; e < 8; ++e) {
        int idx = tid*8 + e;           // 0..1023
        int row = idx >> 5, c = idx & 31;
        float re = Sre[row*33 + c];
        float im = Sim[row*33 + c];
        int k = __popc(c) & 3;
        float a, bb;
        if (k == 0)      { a =  re; bb =  im; }
        else if (k == 1) { a =  im; bb = -re; }
        else if (k == 2) { a = -re; bb = -im; }
        else             { a = -im; bb =  re; }
        g_Rr[idx] = a; g_Ri[idx] = bb;
    }
}

// ================= main kernel: no SMEM, no barriers =================
__global__ __launch_bounds__(128)
void qrnn_main(const float* __restrict__ x,
               const float* __restrict__ hidden,
               float* __restrict__ out)
{
    const int b   = blockIdx.x;
    const int tid = threadIdx.x;

    if (tid < 32) {
        // ---- warp 0: recurrence loop ----
        const int lane = tid;

        // load ROW lane (coalesced float4)
        float Rr[32], Ri[32];
        {
            const float4* pr = (const float4*)(g_Rr + lane*32);
            const float4* pi = (const float4*)(g_Ri + lane*32);
            #pragma unroll
            for (int k = 0; k < 8; ++k) {
                float4 vr = pr[k], vi = pi[k];
                Rr[4*k+0] = vr.x; Rr[4*k+1] = vr.y; Rr[4*k+2] = vr.z; Rr[4*k+3] = vr.w;
                Ri[4*k+0] = vi.x; Ri[4*k+1] = vi.y; Ri[4*k+2] = vi.z; Ri[4*k+3] = vi.w;
            }
        }

        float zf0 = 0.5f*hidden[b*NH + 0];
        float zf1 = 0.5f*hidden[b*NH + 1];
        float zf2 = 0.5f*hidden[b*NH + 2];
        float zf3 = 0.5f*hidden[b*NH + 3];
        float zf4 = 0.5f*hidden[b*NH + 4];

        const float SCALE   = 1073741824.0f;           // 2^30
        const float INV2_31 = 4.656612873077393e-10f;  // 2^-31

        #pragma unroll 1
        for (int t = 0; t < SEQ; ++t) {
            float c0 = __cosf(zf0), s0 = __sinf(zf0);
            float c1 = __cosf(zf1), s1 = __sinf(zf1);
            float c2 = __cosf(zf2), s2 = __sinf(zf2);
            float c3 = __cosf(zf3), s3 = __sinf(zf3);
            float c4 = __cosf(zf4), s4 = __sinf(zf4);

            float g00 = c0*c1, g01 = c0*s1, g10 = s0*c1, g11 = s0*s1;
            float g0 = g00*c2, g1 = g00*s2, g2 = g01*c2, g3 = g01*s2;
            float g4 = g10*c2, g5 = g10*s2, g6 = g11*c2, g7 = g11*s2;
            float h0 = c3*c4, h1 = c3*s4, h2 = s3*c4, h3 = s3*s4;

            float aR0 = 0.f, aR1 = 0.f, aI0 = 0.f, aI1 = 0.f;
            #define GRP(k, g, accR, accI)                                   \
            {                                                               \
                float t0 = fmaf(Rr[4*(k)+1], h1, Rr[4*(k)  ] * h0);         \
                float t1 = fmaf(Rr[4*(k)+3], h3, Rr[4*(k)+2] * h2);         \
                accR = fmaf(g, t0 + t1, accR);                              \
                float u0 = fmaf(Ri[4*(k)+1], h1, Ri[4*(k)  ] * h0);         \
                float u1 = fmaf(Ri[4*(k)+3], h3, Ri[4*(k)+2] * h2);         \
                accI = fmaf(g, u0 + u1, accI);                              \
            }
            GRP(0, g0, aR0, aI0) GRP(1, g1, aR1, aI1)
            GRP(2, g2, aR0, aI0) GRP(3, g3, aR1, aI1)
            GRP(4, g4, aR0, aI0) GRP(5, g5, aR1, aI1)
            GRP(6, g6, aR0, aI0) GRP(7, g7, aR1, aI1)
            #undef GRP
            float nar = aR0 + aR1;
            float nai = aI0 + aI1;

            float p = fmaf(nar, nar, nai*nai);
            int ip = __float2int_rn(p * SCALE);
            int nip = -ip;
            int t0 = __reduce_add_sync(0xffffffffu, (lane & 16) ? nip : ip);
            int t1 = __reduce_add_sync(0xffffffffu, (lane &  8) ? nip : ip);
            int t2 = __reduce_add_sync(0xffffffffu, (lane &  4) ? nip : ip);
            int t3 = __reduce_add_sync(0xffffffffu, (lane &  2) ? nip : ip);
            int t4 = __reduce_add_sync(0xffffffffu, (lane &  1) ? nip : ip);

            zf0 = (float)t0 * INV2_31;
            zf1 = (float)t1 * INV2_31;
            zf2 = (float)t2 * INV2_31;
            zf3 = (float)t3 * INV2_31;
            zf4 = (float)t4 * INV2_31;
        }

        if (lane < NH) {
            float zz = 2.f*zf0;
            zz = (lane == 1) ? 2.f*zf1 : zz;
            zz = (lane == 2) ? 2.f*zf2 : zz;
            zz = (lane == 3) ? 2.f*zf3 : zz;
            zz = (lane == 4) ? 2.f*zf4 : zz;
            out[BATCH*SEQ*NV + b*NH + lane] = zz;
        }

    } else {
        // ---- warps 1-3: closed-form outputs (start immediately, no barriers) ----
        const int t = tid - 32;
        if (t >= SEQ) return;

        const int P = b * SEQ + t;
        const float4* x4 = (const float4*)(x + (size_t)P * FEAT);
        float vals[60];
        #pragma unroll
        for (int k = 0; k < 15; k++) {
            float4 v4 = x4[k];
            vals[4*k+0] = v4.x; vals[4*k+1] = v4.y;
            vals[4*k+2] = v4.z; vals[4*k+3] = v4.w;
        }
        float pooled[6];
        #pragma unroll
        for (int v = 0; v < 6; v++) {
            float s = 0.f;
            #pragma unroll
            for (int j = 0; j < 10; j++) s += vals[v*10 + j];
            pooled[v] = 0.1f * s;
        }
        float mn = pooled[0], mx = pooled[0];
        #pragma unroll
        for (int v = 1; v < 6; v++) {
            mn = fminf(mn, pooled[v]);
            mx = fmaxf(mx, pooled[v]);
        }
        float scale = TWO_PI / (mx - mn + 1e-8f);
        #pragma unroll
        for (int v = 0; v < 6; v++) {
            float a = scale * (pooled[v] - mn);
            float sa, ca;
            sincosf(a, &sa, &ca);
            out[(size_t)P*6 + v] = g_CDE[v] + g_CDE[6+v]*ca + g_CDE[12+v]*sa;
        }
    }
}

extern "C" void kernel_launch(void* const* d_in, const int* in_sizes, int n_in,
                              void* d_out, int out_size) {
    const float* x      = (const float*)d_in[0];
    const float* hidden = (const float*)d_in[1];
    const float* params = (const float*)d_in[2];
    float* out = (float*)d_out;
    qrnn_prep<<<1, 128>>>(params);
    qrnn_main<<<BATCH, 128>>>(x, hidden, out);
}

// round 16
// speedup vs baseline: 1.2429x; 1.2429x over previous
#include <cuda_runtime.h>
#include <math.h>

#define BATCH 128
#define SEQ 48
#define FEAT 60
#define NH 5
#define NV 6
#define TWO_PI 6.2831853071795864769f

struct C2 { float re, im; };
struct M2 { C2 m00, m01, m10, m11; };

__device__ __forceinline__ C2 cmul(C2 a, C2 b) {
    C2 r; r.re = a.re*b.re - a.im*b.im; r.im = a.re*b.im + a.im*b.re; return r;
}
__device__ __forceinline__ C2 cadd(C2 a, C2 b) { C2 r{a.re+b.re, a.im+b.im}; return r; }

// U = RZ(t3)*RY(t2)*RX(t1) — precise trig (used off critical path for C/D/E)
__device__ __forceinline__ M2 fuse_zyx(float t1, float t2, float t3) {
    float c1,s1,c2,s2,c3,s3;
    sincosf(0.5f*t1, &s1, &c1);
    sincosf(0.5f*t2, &s2, &c2);
    sincosf(0.5f*t3, &s3, &c3);
    C2 a00{c1,0.f}, a01{0.f,-s1}, a10{0.f,-s1}, a11{c1,0.f};
    C2 m00{c2*a00.re - s2*a10.re, c2*a00.im - s2*a10.im};
    C2 m01{c2*a01.re - s2*a11.re, c2*a01.im - s2*a11.im};
    C2 m10{s2*a00.re + c2*a10.re, s2*a00.im + c2*a10.im};
    C2 m11{s2*a01.re + c2*a11.re, s2*a01.im + c2*a11.im};
    C2 r0{c3,-s3}, r1{c3,s3};
    M2 u;
    u.m00 = cmul(r0,m00); u.m01 = cmul(r0,m01);
    u.m10 = cmul(r1,m10); u.m11 = cmul(r1,m11);
    return u;
}
// fast-trig variant for hidden gates (critical path)
__device__ __forceinline__ M2 fuse_zyx_fast(float t1, float t2, float t3) {
    float c1,s1,c2,s2,c3,s3;
    __sincosf(0.5f*t1, &s1, &c1);
    __sincosf(0.5f*t2, &s2, &c2);
    __sincosf(0.5f*t3, &s3, &c3);
    C2 a00{c1,0.f}, a01{0.f,-s1}, a10{0.f,-s1}, a11{c1,0.f};
    C2 m00{c2*a00.re - s2*a10.re, c2*a00.im - s2*a10.im};
    C2 m01{c2*a01.re - s2*a11.re, c2*a01.im - s2*a11.im};
    C2 m10{s2*a00.re + c2*a10.re, s2*a00.im + c2*a10.im};
    C2 m11{s2*a01.re + c2*a11.re, s2*a01.im + c2*a11.im};
    C2 r0{c3,-s3}, r1{c3,s3};
    M2 u;
    u.m00 = cmul(r0,m00); u.m01 = cmul(r0,m01);
    u.m10 = cmul(r1,m10); u.m11 = cmul(r1,m11);
    return u;
}
__device__ __forceinline__ M2 mmul(M2 p, M2 q) {
    M2 r;
    r.m00 = cadd(cmul(p.m00,q.m00), cmul(p.m01,q.m10));
    r.m01 = cadd(cmul(p.m00,q.m01), cmul(p.m01,q.m11));
    r.m10 = cadd(cmul(p.m10,q.m00), cmul(p.m11,q.m10));
    r.m11 = cadd(cmul(p.m10,q.m01), cmul(p.m11,q.m11));
    return r;
}

__device__ __forceinline__ M2 load_gate(const float* gm) {
    M2 g;
    g.m00.re = gm[0]; g.m00.im = gm[1];
    g.m01.re = gm[2]; g.m01.im = gm[3];
    g.m10.re = gm[4]; g.m10.im = gm[5];
    g.m11.re = gm[6]; g.m11.im = gm[7];
    return g;
}
// gate entry [r][c] as C2
__device__ __forceinline__ C2 gate_rc(const float* gm, int r, int c) {
    C2 v; v.re = gm[(r*2+c)*2]; v.im = gm[(r*2+c)*2+1]; return v;
}

// ---- cooperative SMEM gate stages: state S[amp][col], stride 33 ----
template<int M>
__device__ __forceinline__ void g1q_s(float* Sre, float* Sim, int col, int w, const float* gm) {
    M2 g = load_gate(gm);
    #pragma unroll
    for (int pp = 0; pp < 4; ++pp) {
        int p = 4*w + pp;
        int i = ((p & ~(M-1)) << 1) | (p & (M-1));
        int j = i | M;
        float ar = Sre[i*33+col], ai = Sim[i*33+col];
        float br = Sre[j*33+col], bi = Sim[j*33+col];
        Sre[i*33+col] = g.m00.re*ar - g.m00.im*ai + g.m01.re*br - g.m01.im*bi;
        Sim[i*33+col] = g.m00.re*ai + g.m00.im*ar + g.m01.re*bi + g.m01.im*br;
        Sre[j*33+col] = g.m10.re*ar - g.m10.im*ai + g.m11.re*br - g.m11.im*bi;
        Sim[j*33+col] = g.m10.re*ai + g.m10.im*ar + g.m11.re*bi + g.m11.im*br;
    }
}
template<int MC, int MT>
__device__ __forceinline__ void gcrx_s(float* Sre, float* Sim, int col, int w, float c, float s) {
    #pragma unroll
    for (int pp = 0; pp < 2; ++pp) {
        int p = 2*w + pp;
        int i = ((p & ~(MT-1)) << 2) | MC | (p & (MT-1));
        int j = i | MT;
        float a0r = Sre[i*33+col], a0i = Sim[i*33+col];
        float a1r = Sre[j*33+col], a1i = Sim[j*33+col];
        Sre[i*33+col] = c*a0r + s*a1i;
        Sim[i*33+col] = c*a0i - s*a1r;
        Sre[j*33+col] = s*a0i + c*a1r;
        Sim[j*33+col] = c*a1i - s*a0r;
    }
}

__global__ __launch_bounds__(128)
void qrnn_kernel(const float* __restrict__ x,
                 const float* __restrict__ hidden,
                 const float* __restrict__ params,
                 float* __restrict__ out)
{
    const int b   = blockIdx.x;
    const int tid = threadIdx.x;
    const int col = tid & 31;
    const int w   = tid >> 5;

    __shared__ float Sre[32*33];
    __shared__ float Sim[32*33];
    __shared__ float GM[10][8];    // h1[0..4] = GM[0..4], h2[0..4] = GM[5..9]
    __shared__ float CXs[8], SXs[8];
    __shared__ float sCc[6], sDd[6], sEe[6];

    // ======== Phase A: hidden-gate trig (fast) ========
    if (tid < 10) {
        int l = tid / 5, q = tid % 5;
        M2 g = fuse_zyx_fast(params[l*37 + 3*q], params[l*37 + 3*q + 1], params[l*37 + 3*q + 2]);
        float* gm = GM[tid];
        gm[0] = g.m00.re; gm[1] = g.m00.im;
        gm[2] = g.m01.re; gm[3] = g.m01.im;
        gm[4] = g.m10.re; gm[5] = g.m10.im;
        gm[6] = g.m11.re; gm[7] = g.m11.im;
    } else if (tid < 18) {
        int k = tid - 10;
        int l = k >> 2, kk = k & 3;
        __sincosf(0.5f*params[l*37 + 15 + kk], &SXs[k], &CXs[k]);
    }
    __syncthreads();

    // ======== init: columns of G1 = product state (replaces 5 gate stages) ========
    {
        const int cb0 = (col >> 4) & 1, cb1 = (col >> 3) & 1, cb2 = (col >> 2) & 1;
        const int cb3 = (col >> 1) & 1, cb4 = col & 1;
        const int b4 = w >> 1, b3 = w & 1;
        C2 pre = cmul(gate_rc(GM[0], b4, cb0), gate_rc(GM[1], b3, cb1));
        C2 mid[4];
        #pragma unroll
        for (int m = 0; m < 4; ++m)
            mid[m] = cmul(gate_rc(GM[2], m >> 1, cb2), gate_rc(GM[3], m & 1, cb3));
        #pragma unroll
        for (int k = 0; k < 8; ++k) {
            C2 a = cmul(cmul(pre, mid[k >> 1]), gate_rc(GM[4], k & 1, cb4));
            int i = 8*w + k;
            Sre[i*33 + col] = a.re;
            Sim[i*33 + col] = a.im;
        }
    }
    __syncthreads();

    // ======== build: CRX0, G2, CRX1 (13 barrier stages) ========
    gcrx_s<16,8>(Sre, Sim, col, w, CXs[0], SXs[0]); __syncthreads();
    gcrx_s< 8,4>(Sre, Sim, col, w, CXs[1], SXs[1]); __syncthreads();
    gcrx_s< 4,2>(Sre, Sim, col, w, CXs[2], SXs[2]); __syncthreads();
    gcrx_s< 2,1>(Sre, Sim, col, w, CXs[3], SXs[3]); __syncthreads();
    g1q_s<16>(Sre, Sim, col, w, GM[5]); __syncthreads();
    g1q_s< 8>(Sre, Sim, col, w, GM[6]); __syncthreads();
    g1q_s< 4>(Sre, Sim, col, w, GM[7]); __syncthreads();
    g1q_s< 2>(Sre, Sim, col, w, GM[8]); __syncthreads();
    g1q_s< 1>(Sre, Sim, col, w, GM[9]); __syncthreads();
    gcrx_s<16,8>(Sre, Sim, col, w, CXs[4], SXs[4]); __syncthreads();
    gcrx_s< 8,4>(Sre, Sim, col, w, CXs[5], SXs[5]); __syncthreads();
    gcrx_s< 4,2>(Sre, Sim, col, w, CXs[6], SXs[6]); __syncthreads();
    gcrx_s< 2,1>(Sre, Sim, col, w, CXs[7], SXs[7]); __syncthreads();

    if (tid < 32) {
        // ======== warp 0: recurrence loop (unchanged R13/R14) ========
        const int lane = tid;

        float Rr[32], Ri[32];
        #pragma unroll
        for (int j = 0; j < 32; ++j) {
            float re = Sre[lane*33 + j];
            float im = Sim[lane*33 + j];
            int k = __popc(j) & 3;
            float a, bb;
            if (k == 0)      { a =  re; bb =  im; }
            else if (k == 1) { a =  im; bb = -re; }
            else if (k == 2) { a = -re; bb = -im; }
            else             { a = -im; bb =  re; }
            Rr[j] = a; Ri[j] = bb;
        }

        float zf0 = 0.5f*hidden[b*NH + 0];
        float zf1 = 0.5f*hidden[b*NH + 1];
        float zf2 = 0.5f*hidden[b*NH + 2];
        float zf3 = 0.5f*hidden[b*NH + 3];
        float zf4 = 0.5f*hidden[b*NH + 4];

        const float SCALE   = 1073741824.0f;           // 2^30
        const float INV2_31 = 4.656612873077393e-10f;  // 2^-31

        #pragma unroll 1
        for (int t = 0; t < SEQ; ++t) {
            float c0 = __cosf(zf0), s0 = __sinf(zf0);
            float c1 = __cosf(zf1), s1 = __sinf(zf1);
            float c2 = __cosf(zf2), s2 = __sinf(zf2);
            float c3 = __cosf(zf3), s3 = __sinf(zf3);
            float c4 = __cosf(zf4), s4 = __sinf(zf4);

            float g00 = c0*c1, g01 = c0*s1, g10 = s0*c1, g11 = s0*s1;
            float g0 = g00*c2, g1 = g00*s2, g2 = g01*c2, g3 = g01*s2;
            float g4 = g10*c2, g5 = g10*s2, g6 = g11*c2, g7 = g11*s2;
            float h0 = c3*c4, h1 = c3*s4, h2 = s3*c4, h3 = s3*s4;

            float aR0 = 0.f, aR1 = 0.f, aI0 = 0.f, aI1 = 0.f;
            #define GRP(k, g, accR, accI)                                   \
            {                                                               \
                float t0 = fmaf(Rr[4*(k)+1], h1, Rr[4*(k)  ] * h0);         \
                float t1 = fmaf(Rr[4*(k)+3], h3, Rr[4*(k)+2] * h2);         \
                accR = fmaf(g, t0 + t1, accR);                              \
                float u0 = fmaf(Ri[4*(k)+1], h1, Ri[4*(k)  ] * h0);         \
                float u1 = fmaf(Ri[4*(k)+3], h3, Ri[4*(k)+2] * h2);         \
                accI = fmaf(g, u0 + u1, accI);                              \
            }
            GRP(0, g0, aR0, aI0) GRP(1, g1, aR1, aI1)
            GRP(2, g2, aR0, aI0) GRP(3, g3, aR1, aI1)
            GRP(4, g4, aR0, aI0) GRP(5, g5, aR1, aI1)
            GRP(6, g6, aR0, aI0) GRP(7, g7, aR1, aI1)
            #undef GRP
            float nar = aR0 + aR1;
            float nai = aI0 + aI1;

            float p = fmaf(nar, nar, nai*nai);
            int ip = __float2int_rn(p * SCALE);
            int nip = -ip;
            int t0 = __reduce_add_sync(0xffffffffu, (lane & 16) ? nip : ip);
            int t1 = __reduce_add_sync(0xffffffffu, (lane &  8) ? nip : ip);
            int t2 = __reduce_add_sync(0xffffffffu, (lane &  4) ? nip : ip);
            int t3 = __reduce_add_sync(0xffffffffu, (lane &  2) ? nip : ip);
            int t4 = __reduce_add_sync(0xffffffffu, (lane &  1) ? nip : ip);

            zf0 = (float)t0 * INV2_31;
            zf1 = (float)t1 * INV2_31;
            zf2 = (float)t2 * INV2_31;
            zf3 = (float)t3 * INV2_31;
            zf4 = (float)t4 * INV2_31;
        }

        if (lane < NH) {
            float zz = 2.f*zf0;
            zz = (lane == 1) ? 2.f*zf1 : zz;
            zz = (lane == 2) ? 2.f*zf2 : zz;
            zz = (lane == 3) ? 2.f*zf3 : zz;
            zz = (lane == 4) ? 2.f*zf4 : zz;
            out[BATCH*SEQ*NV + b*NH + lane] = zz;
        }

    } else {
        // ======== warps 1-3: C/D/E (precise, off warp-0 path) + outputs ========
        if (tid < 38) {
            int q = tid - 32;
            M2 u0 = fuse_zyx(params[19+3*q],    params[20+3*q],    params[21+3*q]);
            M2 u1 = fuse_zyx(params[37+19+3*q], params[37+20+3*q], params[37+21+3*q]);
            M2 M = mmul(u1, u0);
            float h00 = (M.m00.re*M.m00.re + M.m00.im*M.m00.im)
                      - (M.m10.re*M.m10.re + M.m10.im*M.m10.im);
            float h11 = (M.m01.re*M.m01.re + M.m01.im*M.m01.im)
                      - (M.m11.re*M.m11.re + M.m11.im*M.m11.im);
            float imh01 = (M.m00.re*M.m01.im - M.m00.im*M.m01.re)
                        - (M.m10.re*M.m11.im - M.m10.im*M.m11.re);
            sCc[q] = 0.5f*(h00 + h11);
            sDd[q] = 0.5f*(h00 - h11);
            sEe[q] = imh01;
        }
        // named barrier among warps 1-3 only (96 threads)
        asm volatile("bar.sync 1, 96;" ::: "memory");

        const int t = tid - 32;
        if (t >= SEQ) return;

        const int P = b * SEQ + t;
        const float4* x4 = (const float4*)(x + (size_t)P * FEAT);
        float vals[60];
        #pragma unroll
        for (int k = 0; k < 15; k++) {
            float4 v4 = x4[k];
            vals[4*k+0] = v4.x; vals[4*k+1] = v4.y;
            vals[4*k+2] = v4.z; vals[4*k+3] = v4.w;
        }
        float pooled[6];
        #pragma unroll
        for (int v = 0; v < 6; v++) {
            float s = 0.f;
            #pragma unroll
            for (int j = 0; j < 10; j++) s += vals[v*10 + j];
            pooled[v] = 0.1f * s;
        }
        float mn = pooled[0], mx = pooled[0];
        #pragma unroll
        for (int v = 1; v < 6; v++) {
            mn = fminf(mn, pooled[v]);
            mx = fmaxf(mx, pooled[v]);
        }
        float scale = TWO_PI / (mx - mn + 1e-8f);
        #pragma unroll
        for (int v = 0; v < 6; v++) {
            float a = scale * (pooled[v] - mn);
            float sa, ca;
            sincosf(a, &sa, &ca);
            out[(size_t)P*6 + v] = sCc[v] + sDd[v]*ca + sEe[v]*sa;
        }
    }
}

extern "C" void kernel_launch(void* const* d_in, const int* in_sizes, int n_in,
                              void* d_out, int out_size) {
    const float* x      = (const float*)d_in[0];
    const float* hidden = (const float*)d_in[1];
    const float* params = (const float*)d_in[2];
    float* out = (float*)d_out;
    qrnn_kernel<<<BATCH, 128>>>(x, hidden, params, out);
}

// round 17
// speedup vs baseline: 1.3907x; 1.1189x over previous
#include <cuda_runtime.h>
#include <math.h>

#define BATCH 128
#define SEQ 48
#define FEAT 60
#define NH 5
#define NV 6
#define TWO_PI 6.2831853071795864769f

struct C2 { float re, im; };
struct M2 { C2 m00, m01, m10, m11; };

__device__ __forceinline__ C2 cmul(C2 a, C2 b) {
    C2 r; r.re = a.re*b.re - a.im*b.im; r.im = a.re*b.im + a.im*b.re; return r;
}
__device__ __forceinline__ C2 cadd(C2 a, C2 b) { C2 r{a.re+b.re, a.im+b.im}; return r; }

// U = RZ(t3)*RY(t2)*RX(t1) — precise trig (off critical path: C/D/E)
__device__ __forceinline__ M2 fuse_zyx(float t1, float t2, float t3) {
    float c1,s1,c2,s2,c3,s3;
    sincosf(0.5f*t1, &s1, &c1);
    sincosf(0.5f*t2, &s2, &c2);
    sincosf(0.5f*t3, &s3, &c3);
    C2 a00{c1,0.f}, a01{0.f,-s1}, a10{0.f,-s1}, a11{c1,0.f};
    C2 m00{c2*a00.re - s2*a10.re, c2*a00.im - s2*a10.im};
    C2 m01{c2*a01.re - s2*a11.re, c2*a01.im - s2*a11.im};
    C2 m10{s2*a00.re + c2*a10.re, s2*a00.im + c2*a10.im};
    C2 m11{s2*a01.re + c2*a11.re, s2*a01.im + c2*a11.im};
    C2 r0{c3,-s3}, r1{c3,s3};
    M2 u;
    u.m00 = cmul(r0,m00); u.m01 = cmul(r0,m01);
    u.m10 = cmul(r1,m10); u.m11 = cmul(r1,m11);
    return u;
}
__device__ __forceinline__ M2 fuse_zyx_fast(float t1, float t2, float t3) {
    float c1,s1,c2,s2,c3,s3;
    __sincosf(0.5f*t1, &s1, &c1);
    __sincosf(0.5f*t2, &s2, &c2);
    __sincosf(0.5f*t3, &s3, &c3);
    C2 a00{c1,0.f}, a01{0.f,-s1}, a10{0.f,-s1}, a11{c1,0.f};
    C2 m00{c2*a00.re - s2*a10.re, c2*a00.im - s2*a10.im};
    C2 m01{c2*a01.re - s2*a11.re, c2*a01.im - s2*a11.im};
    C2 m10{s2*a00.re + c2*a10.re, s2*a00.im + c2*a10.im};
    C2 m11{s2*a01.re + c2*a11.re, s2*a01.im + c2*a11.im};
    C2 r0{c3,-s3}, r1{c3,s3};
    M2 u;
    u.m00 = cmul(r0,m00); u.m01 = cmul(r0,m01);
    u.m10 = cmul(r1,m10); u.m11 = cmul(r1,m11);
    return u;
}
__device__ __forceinline__ M2 mmul(M2 p, M2 q) {
    M2 r;
    r.m00 = cadd(cmul(p.m00,q.m00), cmul(p.m01,q.m10));
    r.m01 = cadd(cmul(p.m00,q.m01), cmul(p.m01,q.m11));
    r.m10 = cadd(cmul(p.m10,q.m00), cmul(p.m11,q.m10));
    r.m11 = cadd(cmul(p.m10,q.m01), cmul(p.m11,q.m11));
    return r;
}

__device__ __forceinline__ M2 load_gate(const float* gm) {
    M2 g;
    g.m00.re = gm[0]; g.m00.im = gm[1];
    g.m01.re = gm[2]; g.m01.im = gm[3];
    g.m10.re = gm[4]; g.m10.im = gm[5];
    g.m11.re = gm[6]; g.m11.im = gm[7];
    return g;
}
__device__ __forceinline__ C2 gate_rc(const float* gm, int r, int c) {
    C2 v; v.re = gm[(r*2+c)*2]; v.im = gm[(r*2+c)*2+1]; return v;
}

// polynomial trig for |x| <= 0.5 (FMA pipe only; err < 1e-7)
__device__ __forceinline__ void poly_sincos(float x, float& s, float& c) {
    float x2 = x*x;
    float sp = fmaf(x2, -1.9841270e-4f, 8.3333333e-3f);
    sp = fmaf(x2, sp, -1.6666667e-1f);
    s  = x * fmaf(x2, sp, 1.f);
    float cp = fmaf(x2, -1.3888889e-3f, 4.1666667e-2f);
    cp = fmaf(x2, cp, -5.0e-1f);
    c  = fmaf(x2, cp, 1.f);
}

// ---- cooperative SMEM gate stages: state S[amp][col], stride 33 ----
template<int M>
__device__ __forceinline__ void g1q_s(float* Sre, float* Sim, int col, int w, const float* gm) {
    M2 g = load_gate(gm);
    #pragma unroll
    for (int pp = 0; pp < 4; ++pp) {
        int p = 4*w + pp;
        int i = ((p & ~(M-1)) << 1) | (p & (M-1));
        int j = i | M;
        float ar = Sre[i*33+col], ai = Sim[i*33+col];
        float br = Sre[j*33+col], bi = Sim[j*33+col];
        Sre[i*33+col] = g.m00.re*ar - g.m00.im*ai + g.m01.re*br - g.m01.im*bi;
        Sim[i*33+col] = g.m00.re*ai + g.m00.im*ar + g.m01.re*bi + g.m01.im*br;
        Sre[j*33+col] = g.m10.re*ar - g.m10.im*ai + g.m11.re*br - g.m11.im*bi;
        Sim[j*33+col] = g.m10.re*ai + g.m10.im*ar + g.m11.re*bi + g.m11.im*br;
    }
}
template<int MC, int MT>
__device__ __forceinline__ void gcrx_s(float* Sre, float* Sim, int col, int w, float c, float s) {
    #pragma unroll
    for (int pp = 0; pp < 2; ++pp) {
        int p = 2*w + pp;
        int i = ((p & ~(MT-1)) << 2) | MC | (p & (MT-1));
        int j = i | MT;
        float a0r = Sre[i*33+col], a0i = Sim[i*33+col];
        float a1r = Sre[j*33+col], a1i = Sim[j*33+col];
        Sre[i*33+col] = c*a0r + s*a1i;
        Sim[i*33+col] = c*a0i - s*a1r;
        Sre[j*33+col] = s*a0i + c*a1r;
        Sim[j*33+col] = c*a1i - s*a0r;
    }
}

__global__ __launch_bounds__(128)
void qrnn_kernel(const float* __restrict__ x,
                 const float* __restrict__ hidden,
                 const float* __restrict__ params,
                 float* __restrict__ out)
{
    const int b   = blockIdx.x;
    const int tid = threadIdx.x;
    const int col = tid & 31;
    const int w   = tid >> 5;

    __shared__ float Sre[32*33];
    __shared__ float Sim[32*33];
    __shared__ float GM[10][8];
    __shared__ float CXs[8], SXs[8];
    __shared__ float sCc[6], sDd[6], sEe[6];

    // ======== Phase A: hidden-gate trig (fast) ========
    if (tid < 10) {
        int l = tid / 5, q = tid % 5;
        M2 g = fuse_zyx_fast(params[l*37 + 3*q], params[l*37 + 3*q + 1], params[l*37 + 3*q + 2]);
        float* gm = GM[tid];
        gm[0] = g.m00.re; gm[1] = g.m00.im;
        gm[2] = g.m01.re; gm[3] = g.m01.im;
        gm[4] = g.m10.re; gm[5] = g.m10.im;
        gm[6] = g.m11.re; gm[7] = g.m11.im;
    } else if (tid < 18) {
        int k = tid - 10;
        int l = k >> 2, kk = k & 3;
        __sincosf(0.5f*params[l*37 + 15 + kk], &SXs[k], &CXs[k]);
    }
    __syncthreads();

    // ======== init: columns of G1 = product state ========
    {
        const int cb0 = (col >> 4) & 1, cb1 = (col >> 3) & 1, cb2 = (col >> 2) & 1;
        const int cb3 = (col >> 1) & 1, cb4 = col & 1;
        const int b4 = w >> 1, b3 = w & 1;
        C2 pre = cmul(gate_rc(GM[0], b4, cb0), gate_rc(GM[1], b3, cb1));
        C2 mid[4];
        #pragma unroll
        for (int m = 0; m < 4; ++m)
            mid[m] = cmul(gate_rc(GM[2], m >> 1, cb2), gate_rc(GM[3], m & 1, cb3));
        #pragma unroll
        for (int k = 0; k < 8; ++k) {
            C2 a = cmul(cmul(pre, mid[k >> 1]), gate_rc(GM[4], k & 1, cb4));
            int i = 8*w + k;
            Sre[i*33 + col] = a.re;
            Sim[i*33 + col] = a.im;
        }
    }
    __syncthreads();

    // ======== build: CRX0, G2, CRX1 ========
    gcrx_s<16,8>(Sre, Sim, col, w, CXs[0], SXs[0]); __syncthreads();
    gcrx_s< 8,4>(Sre, Sim, col, w, CXs[1], SXs[1]); __syncthreads();
    gcrx_s< 4,2>(Sre, Sim, col, w, CXs[2], SXs[2]); __syncthreads();
    gcrx_s< 2,1>(Sre, Sim, col, w, CXs[3], SXs[3]); __syncthreads();
    g1q_s<16>(Sre, Sim, col, w, GM[5]); __syncthreads();
    g1q_s< 8>(Sre, Sim, col, w, GM[6]); __syncthreads();
    g1q_s< 4>(Sre, Sim, col, w, GM[7]); __syncthreads();
    g1q_s< 2>(Sre, Sim, col, w, GM[8]); __syncthreads();
    g1q_s< 1>(Sre, Sim, col, w, GM[9]); __syncthreads();
    gcrx_s<16,8>(Sre, Sim, col, w, CXs[4], SXs[4]); __syncthreads();
    gcrx_s< 8,4>(Sre, Sim, col, w, CXs[5], SXs[5]); __syncthreads();
    gcrx_s< 4,2>(Sre, Sim, col, w, CXs[6], SXs[6]); __syncthreads();
    gcrx_s< 2,1>(Sre, Sim, col, w, CXs[7], SXs[7]); __syncthreads();

    if (tid < 32) {
        // ======== warp 0: recurrence loop ========
        const int lane = tid;

        // rows scaled by 2^15 so |amp|^2 is already in 2^30 fixed-point
        float Rr[32], Ri[32];
        #pragma unroll
        for (int j = 0; j < 32; ++j) {
            float re = Sre[lane*33 + j] * 32768.0f;
            float im = Sim[lane*33 + j] * 32768.0f;
            int k = __popc(j) & 3;
            float a, bb;
            if (k == 0)      { a =  re; bb =  im; }
            else if (k == 1) { a =  im; bb = -re; }
            else if (k == 2) { a = -re; bb = -im; }
            else             { a = -im; bb =  re; }
            Rr[j] = a; Ri[j] = bb;
        }

        float zf0 = 0.5f*hidden[b*NH + 0];
        float zf1 = 0.5f*hidden[b*NH + 1];
        float zf2 = 0.5f*hidden[b*NH + 2];
        float zf3 = 0.5f*hidden[b*NH + 3];
        float zf4 = 0.5f*hidden[b*NH + 4];

        const float INV2_31 = 4.656612873077393e-10f;  // 2^-31 (fold of 2^-30 and 1/2)

        #pragma unroll 1
        for (int t = 0; t < SEQ; ++t) {
            // ---- trig for h-qubits (3,4) first: h feeds the head of every dot ----
            float c3, s3, c4, s4;
            poly_sincos(zf3, s3, c3);
            poly_sincos(zf4, s4, c4);
            float h0 = c3*c4, h1 = c3*s4, h2 = s3*c4, h3 = s3*s4;

            float c0, s0, c1, s1, c2, s2;
            poly_sincos(zf0, s0, c0);
            poly_sincos(zf1, s1, c1);
            poly_sincos(zf2, s2, c2);
            float g00 = c0*c1, g01 = c0*s1, g10 = s0*c1, g11 = s0*s1;
            float g0 = g00*c2, g1 = g00*s2, g2 = g01*c2, g3 = g01*s2;
            float g4 = g10*c2, g5 = g10*s2, g6 = g11*c2, g7 = g11*s2;

            // ---- matvec: Horner dot4 with h, then acc by g ----
            float aR0 = 0.f, aR1 = 0.f, aI0 = 0.f, aI1 = 0.f;
            #define GRP(k, g, accR, accI)                                   \
            {                                                               \
                float tr = Rr[4*(k)] * h0;                                  \
                tr = fmaf(Rr[4*(k)+1], h1, tr);                             \
                tr = fmaf(Rr[4*(k)+2], h2, tr);                             \
                tr = fmaf(Rr[4*(k)+3], h3, tr);                             \
                accR = fmaf(g, tr, accR);                                   \
                float ti = Ri[4*(k)] * h0;                                  \
                ti = fmaf(Ri[4*(k)+1], h1, ti);                             \
                ti = fmaf(Ri[4*(k)+2], h2, ti);                             \
                ti = fmaf(Ri[4*(k)+3], h3, ti);                             \
                accI = fmaf(g, ti, accI);                                   \
            }
            GRP(0, g0, aR0, aI0) GRP(1, g1, aR1, aI1)
            GRP(2, g2, aR0, aI0) GRP(3, g3, aR1, aI1)
            GRP(4, g4, aR0, aI0) GRP(5, g5, aR1, aI1)
            GRP(6, g6, aR0, aI0) GRP(7, g7, aR1, aI1)
            #undef GRP
            float nar = aR0 + aR1;
            float nai = aI0 + aI1;

            // ---- measure: p already in 2^30 fixed-point scale ----
            int ip = __float2int_rn(fmaf(nar, nar, nai*nai));
            int nip = -ip;
            // h-qubit sums first (their trig heads the next iteration)
            int t3r = __reduce_add_sync(0xffffffffu, (lane &  2) ? nip : ip);
            int t4r = __reduce_add_sync(0xffffffffu, (lane &  1) ? nip : ip);
            int t0r = __reduce_add_sync(0xffffffffu, (lane & 16) ? nip : ip);
            int t1r = __reduce_add_sync(0xffffffffu, (lane &  8) ? nip : ip);
            int t2r = __reduce_add_sync(0xffffffffu, (lane &  4) ? nip : ip);

            zf3 = (float)t3r * INV2_31;
            zf4 = (float)t4r * INV2_31;
            zf0 = (float)t0r * INV2_31;
            zf1 = (float)t1r * INV2_31;
            zf2 = (float)t2r * INV2_31;
        }

        if (lane < NH) {
            float zz = 2.f*zf0;
            zz = (lane == 1) ? 2.f*zf1 : zz;
            zz = (lane == 2) ? 2.f*zf2 : zz;
            zz = (lane == 3) ? 2.f*zf3 : zz;
            zz = (lane == 4) ? 2.f*zf4 : zz;
            out[BATCH*SEQ*NV + b*NH + lane] = zz;
        }

    } else {
        // ======== warps 1-3: C/D/E (precise, off warp-0 path) + outputs ========
        if (tid < 38) {
            int q = tid - 32;
            M2 u0 = fuse_zyx(params[19+3*q],    params[20+3*q],    params[21+3*q]);
            M2 u1 = fuse_zyx(params[37+19+3*q], params[37+20+3*q], params[37+21+3*q]);
            M2 M = mmul(u1, u0);
            float h00 = (M.m00.re*M.m00.re + M.m00.im*M.m00.im)
                      - (M.m10.re*M.m10.re + M.m10.im*M.m10.im);
            float h11 = (M.m01.re*M.m01.re + M.m01.im*M.m01.im)
                      - (M.m11.re*M.m11.re + M.m11.im*M.m11.im);
            float imh01 = (M.m00.re*M.m01.im - M.m00.im*M.m01.re)
                        - (M.m10.re*M.m11.im - M.m10.im*M.m11.re);
            sCc[q] = 0.5f*(h00 + h11);
            sDd[q] = 0.5f*(h00 - h11);
            sEe[q] = imh01;
        }
        asm volatile("bar.sync 1, 96;" ::: "memory");

        const int t = tid - 32;
        if (t >= SEQ) return;

        const int P = b * SEQ + t;
        const float4* x4 = (const float4*)(x + (size_t)P * FEAT);
        float vals[60];
        #pragma unroll
        for (int k = 0; k < 15; k++) {
            float4 v4 = x4[k];
            vals[4*k+0] = v4.x; vals[4*k+1] = v4.y;
            vals[4*k+2] = v4.z; vals[4*k+3] = v4.w;
        }
        float pooled[6];
        #pragma unroll
        for (int v = 0; v < 6; v++) {
            float s = 0.f;
            #pragma unroll
            for (int j = 0; j < 10; j++) s += vals[v*10 + j];
            pooled[v] = 0.1f * s;
        }
        float mn = pooled[0], mx = pooled[0];
        #pragma unroll
        for (int v = 1; v < 6; v++) {
            mn = fminf(mn, pooled[v]);
            mx = fmaxf(mx, pooled[v]);
        }
        float scale = TWO_PI / (mx - mn + 1e-8f);
        #pragma unroll
        for (int v = 0; v < 6; v++) {
            float a = scale * (pooled[v] - mn);
            float sa, ca;
            sincosf(a, &sa, &ca);
            out[(size_t)P*6 + v] = sCc[v] + sDd[v]*ca + sEe[v]*sa;
        }
    }
}

extern "C" void kernel_launch(void* const* d_in, const int* in_sizes, int n_in,
                              void* d_out, int out_size) {
    const float* x      = (const float*)d_in[0];
    const float* hidden = (const float*)d_in[1];
    const float* params = (const float*)d_in[2];
    float* out = (float*)d_out;
    qrnn_kernel<<<BATCH, 128>>>(x, hidden, params, out);
}